// round 16
// baseline (speedup 1.0000x reference)
#include <cuda_runtime.h>
#include <cstdint>
#include <cstddef>

#define NN 512
#define CC 128
typedef unsigned long long ull;
static const size_t PLANE = (size_t)NN * NN;

// ---------------- helpers ----------------------------------------------------
__device__ __forceinline__ float sigmoidf_fast(float x){ return 1.0f/(1.0f+__expf(-x)); }
__device__ __forceinline__ uint32_t f2tf32(float x){
    uint32_t r; asm("cvt.rna.tf32.f32 %0, %1;" : "=r"(r) : "f"(x)); return r;
}
__device__ __forceinline__ float tf32r(float x){ return __uint_as_float(f2tf32(x)); }
__device__ __forceinline__ void mma_tf32(float* d, const uint32_t* a, const uint32_t* b){
    asm volatile("mma.sync.aligned.m16n8k8.row.col.f32.tf32.tf32.f32 "
        "{%0,%1,%2,%3}, {%4,%5,%6,%7}, {%8,%9}, {%0,%1,%2,%3};"
        : "+f"(d[0]), "+f"(d[1]), "+f"(d[2]), "+f"(d[3])
        : "r"(a[0]), "r"(a[1]), "r"(a[2]), "r"(a[3]), "r"(b[0]), "r"(b[1]));
}
__device__ __forceinline__ uint32_t smem_u32(const void* p){
    uint32_t a; asm("{ .reg .u64 t; cvta.to.shared.u64 t, %1; cvt.u32.u64 %0, t; }" : "=r"(a) : "l"(p)); return a;
}
__device__ __forceinline__ void cp16(uint32_t dst, const void* src){
    asm volatile("cp.async.cg.shared.global [%0], [%1], 16;" :: "r"(dst), "l"(src) : "memory");
}
__device__ __forceinline__ void cp_commit(){ asm volatile("cp.async.commit_group;" ::: "memory"); }
template<int N> __device__ __forceinline__ void cp_wait(){
    asm volatile("cp.async.wait_group %0;" :: "n"(N) : "memory");
}

// ---------------- scratch ----------------------------------------------------
__device__ float g_x [(size_t)CC*NN*NN];    // tf32-rounded act, (pos, c)
__device__ float g_mu [NN*NN];
__device__ float g_inv[NN*NN];
__device__ float g_a[(size_t)CC*NN*NN];     // per-channel planes [c][pos] (tf32-rounded)
__device__ float g_b[(size_t)CC*NN*NN];
__device__ float g_t[(size_t)CC*NN*NN];     // triangle result planes [c][i][j] fp32
__device__ float g_sg[(size_t)NN*NN*CC];    // sigmoid(glin), (pos, d) fp32

__device__ float  g_Wc[2][256*128];         // [y][proj128;gate128][c] tf32-rounded
__device__ float  g_Wlr[128*128];           // glin tf32-rounded
__device__ float  g_Wor[128*128];           // out weights tf32-rounded, [d][c]
__device__ float  g_Sp[256], g_Bp[256], g_Sg[256], g_Bg[256];
__device__ float  g_Sl[128], g_Bl[128], g_So[128], g_Bo[128];

// ---------------- k0: LN stats + tf32-rounded act copy -----------------------
__global__ void k0_kernel(const float* __restrict__ act){
    int pos  = blockIdx.x*8 + (threadIdx.x >> 5);
    int lane = threadIdx.x & 31;
    const float4 v = ((const float4*)act)[(size_t)pos*32 + lane];
    float s  = v.x + v.y + v.z + v.w;
    float s2 = v.x*v.x + v.y*v.y + v.z*v.z + v.w*v.w;
    #pragma unroll
    for (int o = 16; o; o >>= 1){
        s  += __shfl_xor_sync(0xffffffffu, s,  o);
        s2 += __shfl_xor_sync(0xffffffffu, s2, o);
    }
    float m   = s * (1.f/128.f);
    float var = s2 * (1.f/128.f) - m*m;
    float4 r = make_float4(tf32r(v.x), tf32r(v.y), tf32r(v.z), tf32r(v.w));
    ((float4*)g_x)[(size_t)pos*32 + lane] = r;
    if (lane == 0){ g_mu[pos] = m; g_inv[pos] = rsqrtf(var + 1e-5f); }
}

// ---------------- prep -------------------------------------------------------
__global__ void prep_kernel(const float* __restrict__ lw, const float* __restrict__ lb,
                            const float* __restrict__ Wp, const float* __restrict__ Wg,
                            const float* __restrict__ cw, const float* __restrict__ cb,
                            const float* __restrict__ Wo, const float* __restrict__ Wl){
    __shared__ float r1[128], r2[128];
    int bid = blockIdx.x;
    int c   = threadIdx.x;
    float sv = 0.f, bv = 0.f;
    float *Sv = nullptr, *Bv = nullptr; int d = 0;

    if (bid < 256){            // proj
        d = bid;
        float sr = tf32r(Wp[d*128 + c] * lw[c]);
        g_Wc[d>>7][(d & 127)*128 + c] = sr;
        sv = sr; bv = Wp[d*128 + c] * lb[c];
        Sv = g_Sp; Bv = g_Bp;
    } else if (bid < 512){     // gate
        d = bid - 256;
        float sr = tf32r(Wg[d*128 + c] * lw[c]);
        g_Wc[d>>7][(128 + (d & 127))*128 + c] = sr;
        sv = sr; bv = Wg[d*128 + c] * lb[c];
        Sv = g_Sg; Bv = g_Bg;
    } else if (bid < 640){     // glin
        d = bid - 512;
        float sr = tf32r(Wl[d*128 + c] * lw[c]);
        g_Wlr[d*128 + c] = sr;
        sv = sr; bv = Wl[d*128 + c] * lb[c];
        Sv = g_Sl; Bv = g_Bl;
    } else {                   // out (tf32-rounded for mma k3)
        d = bid - 640;
        float sr = tf32r(Wo[d*128 + c] * cw[c]);
        g_Wor[d*128 + c] = sr;
        sv = sr; bv = Wo[d*128 + c] * cb[c];
        Sv = g_So; Bv = g_Bo;
    }
    r1[c] = sv; r2[c] = bv;
    __syncthreads();
    for (int s = 64; s > 0; s >>= 1){
        if (c < s){ r1[c] += r1[c+s]; r2[c] += r2[c+s]; }
        __syncthreads();
    }
    if (c == 0){ Sv[d] = r1[0]; Bv[d] = r2[0]; }
}

// ---------------- k1pg: proj+gate, 3-stage pipeline, 512 threads -------------
// smem: A[3][128*36] @0 (55296) | B[3][256*36] @55296 (110592) |
//       consts @165888: smu|sinv|cS1|cB1|cS2|cB2|smk (512 each) => 169472
#define K1PG_SMEM 169472

__global__ void __launch_bounds__(512, 1)
k1pg_kernel(const float* __restrict__ mask){
    extern __shared__ char sm[];
    float* smu  = (float*)(sm + 165888);
    float* sinv = (float*)(sm + 166400);
    float* cS1  = (float*)(sm + 166912);
    float* cB1  = (float*)(sm + 167424);
    float* cS2  = (float*)(sm + 167936);
    float* cB2  = (float*)(sm + 168448);
    float* smk  = (float*)(sm + 168960);
    uint32_t sbase = smem_u32(sm);

    int t = threadIdx.x, wid = t >> 5, lane = t & 31;
    int g = lane >> 2, t4 = lane & 3;
    int WM = (wid >> 2) * 32, WN = (wid & 3) * 32;
    int m0 = blockIdx.x * 128;
    int y  = blockIdx.y;

    if (t < 128){
        smu[t]  = g_mu[m0 + t];
        sinv[t] = g_inv[m0 + t];
        smk[t]  = mask[m0 + t];
        int d   = y*128 + t;
        cS1[t] = g_Sp[d]; cB1[t] = g_Bp[d];
        cS2[t] = g_Sg[d]; cB2[t] = g_Bg[d];
    }

    const float* Asrc = g_x + (size_t)m0 * 128;
    const float* Bsrc = &g_Wc[y][0];

    int arow = t >> 2, af4 = (t & 3) * 2;
    int brow = t >> 1, bf4 = (t & 1) * 4;

    #define K1_LOAD(kb, buf) do {                                              \
        uint32_t adst = sbase + (buf)*18432 + (arow*36)*4;                     \
        const float* asp = Asrc + (size_t)arow*128 + (kb)*32;                  \
        _Pragma("unroll")                                                      \
        for (int u = 0; u < 2; u++) cp16(adst + (af4+u)*16, asp + (af4+u)*4);  \
        uint32_t bdst = sbase + 55296 + (buf)*36864 + (brow*36)*4;             \
        const float* bsp = Bsrc + (size_t)brow*128 + (kb)*32;                  \
        _Pragma("unroll")                                                      \
        for (int u = 0; u < 4; u++) cp16(bdst + (bf4+u)*16, bsp + (bf4+u)*4);  \
    } while(0)

    float accP[2][4][4], accG[2][4][4];
    #pragma unroll
    for (int mi = 0; mi < 2; mi++)
        #pragma unroll
        for (int ni = 0; ni < 4; ni++)
            #pragma unroll
            for (int r = 0; r < 4; r++){ accP[mi][ni][r] = 0.f; accG[mi][ni][r] = 0.f; }

    K1_LOAD(0, 0); cp_commit();
    K1_LOAD(1, 1); cp_commit();

    #pragma unroll
    for (int kb = 0; kb < 4; kb++){
        if (kb + 1 < 4) cp_wait<1>(); else cp_wait<0>();
        __syncthreads();                      // buf kb landed; compute(kb-1) done
        if (kb + 2 < 4){ K1_LOAD(kb+2, (kb+2)%3); cp_commit(); }

        const uint32_t* Au = (const uint32_t*)(sm + (kb%3)*18432);
        const uint32_t* Bu = (const uint32_t*)(sm + 55296 + (kb%3)*36864);
        #pragma unroll
        for (int k8 = 0; k8 < 4; k8++){
            int kof = k8*8 + t4;
            uint32_t af[2][4];
            #pragma unroll
            for (int mi = 0; mi < 2; mi++){
                int base = (WM + mi*16 + g)*36 + kof;
                af[mi][0] = Au[base];         af[mi][1] = Au[base + 8*36];
                af[mi][2] = Au[base + 4];     af[mi][3] = Au[base + 8*36 + 4];
            }
            #pragma unroll
            for (int ni = 0; ni < 4; ni++){
                int bbP = (WN + ni*8 + g)*36 + kof;
                int bbG = bbP + 128*36;
                uint32_t bfP[2] = { Bu[bbP], Bu[bbP + 4] };
                uint32_t bfG[2] = { Bu[bbG], Bu[bbG + 4] };
                #pragma unroll
                for (int mi = 0; mi < 2; mi++){
                    mma_tf32(accP[mi][ni], af[mi], bfP);
                    mma_tf32(accG[mi][ni], af[mi], bfG);
                }
            }
        }
    }
    #undef K1_LOAD

    float* dst = (y == 0) ? g_a : g_b;
    #pragma unroll
    for (int mi = 0; mi < 2; mi++){
        int m = WM + mi*16 + g;
        size_t pos0 = (size_t)(m0 + m), pos1 = pos0 + 8;
        float mu0 = smu[m],   iv0 = sinv[m],   mk0 = smk[m];
        float mu1 = smu[m+8], iv1 = sinv[m+8], mk1 = smk[m+8];
        #pragma unroll
        for (int ni = 0; ni < 4; ni++){
            int dl = WN + ni*8 + 2*t4, dl1 = dl + 1;
            float S0 = cS1[dl], S1 = cS1[dl1], B0 = cB1[dl], B1 = cB1[dl1];
            float G0 = cS2[dl], G1 = cS2[dl1], H0 = cB2[dl], H1 = cB2[dl1];
            float p00 = iv0*(accP[mi][ni][0] - mu0*S0) + B0;
            float p01 = iv0*(accP[mi][ni][1] - mu0*S1) + B1;
            float p10 = iv1*(accP[mi][ni][2] - mu1*S0) + B0;
            float p11 = iv1*(accP[mi][ni][3] - mu1*S1) + B1;
            float q00 = iv0*(accG[mi][ni][0] - mu0*G0) + H0;
            float q01 = iv0*(accG[mi][ni][1] - mu0*G1) + H1;
            float q10 = iv1*(accG[mi][ni][2] - mu1*G0) + H0;
            float q11 = iv1*(accG[mi][ni][3] - mu1*G1) + H1;
            dst[(size_t)dl *PLANE + pos0] = tf32r(p00*mk0*sigmoidf_fast(q00));
            dst[(size_t)dl1*PLANE + pos0] = tf32r(p01*mk0*sigmoidf_fast(q01));
            dst[(size_t)dl *PLANE + pos1] = tf32r(p10*mk1*sigmoidf_fast(q10));
            dst[(size_t)dl1*PLANE + pos1] = tf32r(p11*mk1*sigmoidf_fast(q11));
        }
    }
}

// ---------------- merged kernel: k2 (bids 0..1023) + k1gl (bids 1024..3071) --
// k2 role smem:  A[3][128*36] @0 (55296) | B[3][256*36] @55296 (110592) = 165888
// k1gl role smem: A[3][128*36] @0 | B[3][128*36] @55296 (55296) |
//                 sgs @110592 (66560) | consts @177152 (2048) = 179200
#define KM_SMEM 179200

__global__ void __launch_bounds__(512, 1)
k2gl_kernel(){
    extern __shared__ char sm[];
    uint32_t sbase = smem_u32(sm);

    int t = threadIdx.x, wid = t >> 5, lane = t & 31;
    int g = lane >> 2, t4 = lane & 3;
    int bid = blockIdx.x;

    if (bid < 1024){
        // ================= k2 role: triangle GEMM, 3-stage pipeline ===========
        int WM = (wid >> 2) * 32, WN = (wid & 3) * 64;
        int c  = bid >> 3;
        int i0 = ((bid >> 1) & 3) * 128;
        int j0 = (bid & 1) * 256;
        const float* Ap = g_a + (size_t)c*PLANE + (size_t)i0*NN;
        const float* Bp = g_b + (size_t)c*PLANE + (size_t)j0*NN;

        int arow = t >> 2, af4 = (t & 3) * 2;
        int brow = t >> 1, bf4 = (t & 1) * 4;

        #define K2_LOAD(kb, buf) do {                                              \
            uint32_t adst = sbase + (buf)*18432 + (arow*36)*4;                     \
            const float* asp = Ap + (size_t)arow*NN + (kb)*32;                     \
            _Pragma("unroll")                                                      \
            for (int u = 0; u < 2; u++) cp16(adst + (af4+u)*16, asp + (af4+u)*4);  \
            uint32_t bdst = sbase + 55296 + (buf)*36864 + (brow*36)*4;             \
            const float* bsp = Bp + (size_t)brow*NN + (kb)*32;                     \
            _Pragma("unroll")                                                      \
            for (int u = 0; u < 4; u++) cp16(bdst + (bf4+u)*16, bsp + (bf4+u)*4);  \
        } while(0)

        float acc[2][8][4];
        #pragma unroll
        for (int mi = 0; mi < 2; mi++)
            #pragma unroll
            for (int ni = 0; ni < 8; ni++)
                #pragma unroll
                for (int r = 0; r < 4; r++) acc[mi][ni][r] = 0.f;

        K2_LOAD(0, 0); cp_commit();
        K2_LOAD(1, 1); cp_commit();

        for (int kb = 0; kb < 16; kb++){
            if (kb + 1 < 16) cp_wait<1>(); else cp_wait<0>();
            __syncthreads();
            if (kb + 2 < 16){ K2_LOAD(kb+2, (kb+2)%3); cp_commit(); }

            const uint32_t* Au = (const uint32_t*)(sm + (kb%3)*18432);
            const uint32_t* Bu = (const uint32_t*)(sm + 55296 + (kb%3)*36864);
            #pragma unroll
            for (int k8 = 0; k8 < 4; k8++){
                int kof = k8*8 + t4;
                uint32_t af[2][4];
                #pragma unroll
                for (int mi = 0; mi < 2; mi++){
                    int base = (WM + mi*16 + g)*36 + kof;
                    af[mi][0] = Au[base];         af[mi][1] = Au[base + 8*36];
                    af[mi][2] = Au[base + 4];     af[mi][3] = Au[base + 8*36 + 4];
                }
                uint32_t bf[8][2];
                #pragma unroll
                for (int ni = 0; ni < 8; ni++){
                    int bb = (WN + ni*8 + g)*36 + kof;
                    bf[ni][0] = Bu[bb]; bf[ni][1] = Bu[bb + 4];
                }
                #pragma unroll
                for (int mi = 0; mi < 2; mi++)
                    #pragma unroll
                    for (int ni = 0; ni < 8; ni++)
                        mma_tf32(acc[mi][ni], af[mi], bf[ni]);
            }
        }
        #undef K2_LOAD

        float* Tp = g_t + (size_t)c*PLANE;
        #pragma unroll
        for (int mi = 0; mi < 2; mi++){
            int r0 = i0 + WM + mi*16 + g;
            #pragma unroll
            for (int ni = 0; ni < 8; ni++){
                int cc = j0 + WN + ni*8 + 2*t4;
                *(float2*)(Tp + (size_t)r0*NN + cc)     = make_float2(acc[mi][ni][0], acc[mi][ni][1]);
                *(float2*)(Tp + (size_t)(r0+8)*NN + cc) = make_float2(acc[mi][ni][2], acc[mi][ni][3]);
            }
        }
    } else {
        // ================= k1gl role: glin gate, 3-stage pipeline =============
        float* sgs  = (float*)(sm + 110592);
        float* smu  = (float*)(sm + 177152);
        float* sinv = (float*)(sm + 177664);
        float* cS1  = (float*)(sm + 178176);
        float* cB1  = (float*)(sm + 178688);

        int WM = (wid >> 2) * 32, WN = (wid & 3) * 32;
        int m0 = (bid - 1024) * 128;

        if (t < 128){
            smu[t]  = g_mu[m0 + t];
            sinv[t] = g_inv[m0 + t];
            cS1[t] = g_Sl[t]; cB1[t] = g_Bl[t];
        }

        const float* Asrc = g_x + (size_t)m0 * 128;
        int arow = t >> 2, af4 = (t & 3) * 2;

        #define K1G_LOAD(kb, buf) do {                                             \
            uint32_t adst = sbase + (buf)*18432 + (arow*36)*4;                     \
            const float* asp = Asrc + (size_t)arow*128 + (kb)*32;                  \
            _Pragma("unroll")                                                      \
            for (int u = 0; u < 2; u++) cp16(adst + (af4+u)*16, asp + (af4+u)*4);  \
            uint32_t bdst = sbase + 55296 + (buf)*18432 + (arow*36)*4;             \
            const float* bsp = g_Wlr + (size_t)arow*128 + (kb)*32;                 \
            _Pragma("unroll")                                                      \
            for (int u = 0; u < 2; u++) cp16(bdst + (af4+u)*16, bsp + (af4+u)*4);  \
        } while(0)

        float acc[2][4][4];
        #pragma unroll
        for (int mi = 0; mi < 2; mi++)
            #pragma unroll
            for (int ni = 0; ni < 4; ni++)
                #pragma unroll
                for (int r = 0; r < 4; r++) acc[mi][ni][r] = 0.f;

        K1G_LOAD(0, 0); cp_commit();
        K1G_LOAD(1, 1); cp_commit();

        #pragma unroll
        for (int kb = 0; kb < 4; kb++){
            if (kb + 1 < 4) cp_wait<1>(); else cp_wait<0>();
            __syncthreads();
            if (kb + 2 < 4){ K1G_LOAD(kb+2, (kb+2)%3); cp_commit(); }

            const uint32_t* Au = (const uint32_t*)(sm + (kb%3)*18432);
            const uint32_t* Bu = (const uint32_t*)(sm + 55296 + (kb%3)*18432);
            #pragma unroll
            for (int k8 = 0; k8 < 4; k8++){
                int kof = k8*8 + t4;
                uint32_t af[2][4];
                #pragma unroll
                for (int mi = 0; mi < 2; mi++){
                    int base = (WM + mi*16 + g)*36 + kof;
                    af[mi][0] = Au[base];         af[mi][1] = Au[base + 8*36];
                    af[mi][2] = Au[base + 4];     af[mi][3] = Au[base + 8*36 + 4];
                }
                #pragma unroll
                for (int ni = 0; ni < 4; ni++){
                    int bb = (WN + ni*8 + g)*36 + kof;
                    uint32_t bf[2] = { Bu[bb], Bu[bb + 4] };
                    #pragma unroll
                    for (int mi = 0; mi < 2; mi++)
                        mma_tf32(acc[mi][ni], af[mi], bf);
                }
            }
        }
        #undef K1G_LOAD

        __syncthreads();                      // all MMA reads done before sgs reuse
        #pragma unroll
        for (int mi = 0; mi < 2; mi++){
            int m = WM + mi*16 + g;
            float mu0 = smu[m],   iv0 = sinv[m];
            float mu1 = smu[m+8], iv1 = sinv[m+8];
            #pragma unroll
            for (int ni = 0; ni < 4; ni++){
                int dl = WN + ni*8 + 2*t4, dl1 = dl + 1;
                float S0 = cS1[dl], S1 = cS1[dl1], B0 = cB1[dl], B1 = cB1[dl1];
                sgs[m*130 + dl]      = sigmoidf_fast(iv0*(acc[mi][ni][0] - mu0*S0) + B0);
                sgs[m*130 + dl1]     = sigmoidf_fast(iv0*(acc[mi][ni][1] - mu0*S1) + B1);
                sgs[(m+8)*130 + dl]  = sigmoidf_fast(iv1*(acc[mi][ni][2] - mu1*S0) + B0);
                sgs[(m+8)*130 + dl1] = sigmoidf_fast(iv1*(acc[mi][ni][3] - mu1*S1) + B1);
            }
        }
        __syncthreads();
        float* dst = g_sg + (size_t)m0 * 128;
        #pragma unroll
        for (int u = 0; u < 32; u++){
            int idx = t + u*512;
            int m = idx >> 7, d = idx & 127;
            dst[idx] = sgs[m*130 + d];
        }
    }
}

// ---------------- k3: tf32 mma out-GEMM + LN-fold + gate (R9) ----------------
#define K3_SMEM 70656

__global__ void __launch_bounds__(256, 2)
k3_kernel(float* __restrict__ out){
    extern __shared__ char sm[];
    float* xs  = (float*)sm;                 // [c 64][pos 128+4]
    float* ws  = (float*)(sm + 33792);       // [d 128][c 64+4]
    float* sS1 = (float*)(sm + 68608);
    float* sS2 = (float*)(sm + 69120);
    float* cS  = (float*)(sm + 69632);
    float* cB  = (float*)(sm + 70144);
    const uint32_t* wsu = (const uint32_t*)ws;
    uint32_t sbase = smem_u32(sm);

    int t = threadIdx.x, wid = t >> 5, lane = t & 31;
    int g = lane >> 2, t4 = lane & 3;
    int WM = (wid >> 2) * 64, WN = (wid & 3) * 32;
    int pos0 = blockIdx.x * 128;

    if (t < 128){ cS[t] = g_So[t]; cB[t] = g_Bo[t]; }

    float acc[4][4][4];
    #pragma unroll
    for (int mi = 0; mi < 4; mi++)
        #pragma unroll
        for (int ni = 0; ni < 4; ni++)
            #pragma unroll
            for (int r = 0; r < 4; r++) acc[mi][ni][r] = 0.f;

    for (int cc = 0; cc < 2; cc++){
        #pragma unroll
        for (int u = 0; u < 8; u++){
            int idx = t + u*256;
            int row = idx >> 5, f4 = idx & 31;
            cp16(sbase + (row*132 + f4*4)*4,
                 g_t + (size_t)(cc*64 + row)*PLANE + pos0 + f4*4);
        }
        #pragma unroll
        for (int u = 0; u < 8; u++){
            int idx = t + u*256;
            int row = idx >> 4, f4 = idx & 15;
            cp16(sbase + 33792 + (row*68 + f4*4)*4,
                 g_Wor + (size_t)row*128 + cc*64 + f4*4);
        }
        cp_commit(); cp_wait<0>();
        __syncthreads();

        if (t < 128){
            float s = 0.f, q = 0.f;
            #pragma unroll 8
            for (int c = 0; c < 64; c++){ float v = xs[c*132 + t]; s += v; q += v*v; }
            if (cc == 0){ sS1[t] = s; sS2[t] = q; }
            else        { sS1[t] += s; sS2[t] += q; }
        }

        #pragma unroll
        for (int k8 = 0; k8 < 8; k8++){
            int kof = k8*8 + t4;
            uint32_t bfr[4][2];
            #pragma unroll
            for (int ni = 0; ni < 4; ni++){
                int bb = (WN + ni*8 + g)*68 + kof;
                bfr[ni][0] = wsu[bb]; bfr[ni][1] = wsu[bb + 4];
            }
            #pragma unroll
            for (int mi = 0; mi < 4; mi++){
                int m = WM + mi*16 + g;
                float x0 = xs[kof*132 + m],       x1 = xs[kof*132 + m + 8];
                float x2 = xs[(kof+4)*132 + m],   x3 = xs[(kof+4)*132 + m + 8];
                uint32_t ah[4] = { f2tf32(x0), f2tf32(x1), f2tf32(x2), f2tf32(x3) };
                #pragma unroll
                for (int ni = 0; ni < 4; ni++)
                    mma_tf32(acc[mi][ni], ah, bfr[ni]);
            }
        }
        __syncthreads();
    }

    const float* sgp = g_sg + (size_t)pos0 * 128;
    float* outp = out + (size_t)pos0 * 128;
    #pragma unroll
    for (int mi = 0; mi < 4; mi++){
        int m = WM + mi*16 + g;
        float mu0 = sS1[m]   * (1.f/128.f);
        float mu1 = sS1[m+8] * (1.f/128.f);
        float iv0 = rsqrtf(sS2[m]  *(1.f/128.f) - mu0*mu0 + 1e-5f);
        float iv1 = rsqrtf(sS2[m+8]*(1.f/128.f) - mu1*mu1 + 1e-5f);
        #pragma unroll
        for (int ni = 0; ni < 4; ni++){
            int dl = WN + ni*8 + 2*t4, dl1 = dl + 1;
            float S0 = cS[dl], S1 = cS[dl1], B0 = cB[dl], B1 = cB[dl1];
            float2 sg0 = *(const float2*)(sgp + (size_t)m*128 + dl);
            float2 sg1 = *(const float2*)(sgp + (size_t)(m+8)*128 + dl);
            float o00 = (iv0*(acc[mi][ni][0] - mu0*S0) + B0) * sg0.x;
            float o01 = (iv0*(acc[mi][ni][1] - mu0*S1) + B1) * sg0.y;
            float o10 = (iv1*(acc[mi][ni][2] - mu1*S0) + B0) * sg1.x;
            float o11 = (iv1*(acc[mi][ni][3] - mu1*S1) + B1) * sg1.y;
            *(float2*)(outp + (size_t)m*128 + dl)     = make_float2(o00, o01);
            *(float2*)(outp + (size_t)(m+8)*128 + dl) = make_float2(o10, o11);
        }
    }
}

// ---------------- launch -----------------------------------------------------
extern "C" void kernel_launch(void* const* d_in, const int* in_sizes, int n_in,
                              void* d_out, int out_size){
    const float* act  = (const float*)d_in[0];
    const float* mask = (const float*)d_in[1];
    const float* lnw  = (const float*)d_in[2];
    const float* lnb  = (const float*)d_in[3];
    const float* Wp   = (const float*)d_in[4];
    const float* Wg   = (const float*)d_in[5];
    const float* lcw  = (const float*)d_in[6];
    const float* lcb  = (const float*)d_in[7];
    const float* Wo   = (const float*)d_in[8];
    const float* Wl   = (const float*)d_in[9];

    cudaFuncSetAttribute(k1pg_kernel, cudaFuncAttributeMaxDynamicSharedMemorySize, K1PG_SMEM);
    cudaFuncSetAttribute(k2gl_kernel, cudaFuncAttributeMaxDynamicSharedMemorySize, KM_SMEM);
    cudaFuncSetAttribute(k3_kernel,   cudaFuncAttributeMaxDynamicSharedMemorySize, K3_SMEM);

    prep_kernel<<<768, 128>>>(lnw, lnb, Wp, Wg, lcw, lcb, Wo, Wl);
    k0_kernel<<<32768, 256>>>(act);
    k1pg_kernel<<<dim3(2048, 2), 512, K1PG_SMEM>>>(mask);
    k2gl_kernel<<<3072, 512, KM_SMEM>>>();      // k2 (bids 0..1023) + k1gl (1024..3071)
    k3_kernel<<<2048, 256, K3_SMEM>>>((float*)d_out);
}

// round 17
// speedup vs baseline: 1.2258x; 1.2258x over previous
#include <cuda_runtime.h>
#include <cstdint>
#include <cstddef>

#define NN 512
#define CC 128
typedef unsigned long long ull;
static const size_t PLANE = (size_t)NN * NN;      // 262144
#define GX_KB 8388608                             // g_x k-block stride (floats)

// ---------------- helpers ----------------------------------------------------
__device__ __forceinline__ float sigmoidf_fast(float x){ return 1.0f/(1.0f+__expf(-x)); }
__device__ __forceinline__ uint32_t f2tf32(float x){
    uint32_t r; asm("cvt.rna.tf32.f32 %0, %1;" : "=r"(r) : "f"(x)); return r;
}
__device__ __forceinline__ float tf32r(float x){ return __uint_as_float(f2tf32(x)); }
__device__ __forceinline__ void mma_tf32(float* d, const uint32_t* a, const uint32_t* b){
    asm volatile("mma.sync.aligned.m16n8k8.row.col.f32.tf32.tf32.f32 "
        "{%0,%1,%2,%3}, {%4,%5,%6,%7}, {%8,%9}, {%0,%1,%2,%3};"
        : "+f"(d[0]), "+f"(d[1]), "+f"(d[2]), "+f"(d[3])
        : "r"(a[0]), "r"(a[1]), "r"(a[2]), "r"(a[3]), "r"(b[0]), "r"(b[1]));
}
__device__ __forceinline__ uint32_t smem_u32(const void* p){
    uint32_t a; asm("{ .reg .u64 t; cvta.to.shared.u64 t, %1; cvt.u32.u64 %0, t; }" : "=r"(a) : "l"(p)); return a;
}
__device__ __forceinline__ void cp16(uint32_t dst, const void* src){
    asm volatile("cp.async.cg.shared.global [%0], [%1], 16;" :: "r"(dst), "l"(src) : "memory");
}
__device__ __forceinline__ void cp_commit(){ asm volatile("cp.async.commit_group;" ::: "memory"); }
template<int N> __device__ __forceinline__ void cp_wait(){
    asm volatile("cp.async.wait_group %0;" :: "n"(N) : "memory");
}
// bulk copy: one instruction moves a whole contiguous chunk
__device__ __forceinline__ void bulk_g2s(uint32_t sa, const void* gp, uint32_t bytes, uint32_t mb){
    asm volatile("cp.async.bulk.shared::cta.global.mbarrier::complete_tx::bytes [%0], [%1], %2, [%3];"
        :: "r"(sa), "l"(gp), "r"(bytes), "r"(mb) : "memory");
}
#define MBARRIER_INIT(addr, cnt) \
    asm volatile("mbarrier.init.shared.b64 [%0], %1;" :: "r"(addr), "r"((uint32_t)(cnt)) : "memory")
#define MBARRIER_EXPECT_TX(addr, bytes) \
    asm volatile("mbarrier.arrive.expect_tx.shared.b64 _, [%0], %1;" :: "r"(addr), "r"((uint32_t)(bytes)) : "memory")
#define MBARRIER_WAIT_PARITY(addr, par) do {                                   \
    uint32_t _m = (addr); uint32_t _p = (par); uint32_t _done;                 \
    asm volatile("{\n\t.reg .pred p;\n\t"                                      \
        "mbarrier.try_wait.parity.acquire.cta.shared::cta.b64 p, [%1], %2;\n\t"\
        "selp.b32 %0, 1, 0, p;\n\t}" : "=r"(_done) : "r"(_m), "r"(_p) : "memory"); \
    if (!_done){                                                               \
        asm volatile("{\n\t.reg .pred P1;\n\t"                                 \
        "WL_%=:\n\t"                                                           \
        "mbarrier.try_wait.parity.acquire.cta.shared::cta.b64 P1, [%0], %1, 0x989680;\n\t" \
        "@P1 bra.uni WD_%=;\n\t"                                               \
        "bra.uni WL_%=;\n\t"                                                   \
        "WD_%=:\n\t}" :: "r"(_m), "r"(_p) : "memory");                         \
    } } while(0)

// ---------------- scratch ----------------------------------------------------
// k-blocked rotated layouts (rotation: col' = (k32 + 4*(row&7)) & 31)
__device__ float g_x [(size_t)CC*NN*NN];    // [kb4][pos][32]
__device__ float g_mu [NN*NN];
__device__ float g_inv[NN*NN];
__device__ float g_a[(size_t)CC*NN*NN];     // [c][kb16][i][32]
__device__ float g_b[(size_t)CC*NN*NN];     // [c][kb16][j][32]
__device__ float g_t[(size_t)CC*NN*NN];     // triangle result planes [c][i][j] fp32
__device__ float g_sg[(size_t)NN*NN*CC];    // sigmoid(glin), (pos, d) fp32

__device__ float  g_Wc[2][256*128];         // [y][kb4][proj128;gate128][32] rotated
__device__ float  g_Wlr[128*128];           // [kb4][d][32] rotated
__device__ float  g_Wor[128*128];           // out weights tf32-rounded, [d][c] (k3, unchanged)
__device__ float  g_Sp[256], g_Bp[256], g_Sg[256], g_Bg[256];
__device__ float  g_Sl[128], g_Bl[128], g_So[128], g_Bo[128];

// ---------------- k0: LN stats + tf32-rounded act copy (k-blocked) -----------
__global__ void k0_kernel(const float* __restrict__ act){
    int pos  = blockIdx.x*8 + (threadIdx.x >> 5);
    int lane = threadIdx.x & 31;
    const float4 v = ((const float4*)act)[(size_t)pos*32 + lane];
    float s  = v.x + v.y + v.z + v.w;
    float s2 = v.x*v.x + v.y*v.y + v.z*v.z + v.w*v.w;
    #pragma unroll
    for (int o = 16; o; o >>= 1){
        s  += __shfl_xor_sync(0xffffffffu, s,  o);
        s2 += __shfl_xor_sync(0xffffffffu, s2, o);
    }
    float m   = s * (1.f/128.f);
    float var = s2 * (1.f/128.f) - m*m;
    float4 r = make_float4(tf32r(v.x), tf32r(v.y), tf32r(v.z), tf32r(v.w));
    // c = 4*lane; kb = c>>5 = lane>>3; k32 base = 4*(lane&7); rotate by pos&7
    int kb  = lane >> 3;
    int col = ((lane & 7)*4 + 4*(pos & 7)) & 31;   // multiple of 4, no wrap within float4
    *(float4*)(g_x + (size_t)kb*GX_KB + (size_t)pos*32 + col) = r;
    if (lane == 0){ g_mu[pos] = m; g_inv[pos] = rsqrtf(var + 1e-5f); }
}

// ---------------- prep -------------------------------------------------------
__global__ void prep_kernel(const float* __restrict__ lw, const float* __restrict__ lb,
                            const float* __restrict__ Wp, const float* __restrict__ Wg,
                            const float* __restrict__ cw, const float* __restrict__ cb,
                            const float* __restrict__ Wo, const float* __restrict__ Wl){
    __shared__ float r1[128], r2[128];
    int bid = blockIdx.x;
    int c   = threadIdx.x;
    int kb  = c >> 5, k32 = c & 31;
    float sv = 0.f, bv = 0.f;
    float *Sv = nullptr, *Bv = nullptr; int d = 0;

    if (bid < 256){            // proj -> g_Wc rows 0..127 of y block
        d = bid;
        float sr = tf32r(Wp[d*128 + c] * lw[c]);
        int dd = d & 127;
        int col = (k32 + 4*(dd & 7)) & 31;
        g_Wc[d>>7][kb*8192 + dd*32 + col] = sr;
        sv = sr; bv = Wp[d*128 + c] * lb[c];
        Sv = g_Sp; Bv = g_Bp;
    } else if (bid < 512){     // gate -> rows 128..255
        d = bid - 256;
        float sr = tf32r(Wg[d*128 + c] * lw[c]);
        int dd = 128 + (d & 127);
        int col = (k32 + 4*(dd & 7)) & 31;
        g_Wc[d>>7][kb*8192 + dd*32 + col] = sr;
        sv = sr; bv = Wg[d*128 + c] * lb[c];
        Sv = g_Sg; Bv = g_Bg;
    } else if (bid < 640){     // glin
        d = bid - 512;
        float sr = tf32r(Wl[d*128 + c] * lw[c]);
        int col = (k32 + 4*(d & 7)) & 31;
        g_Wlr[kb*4096 + d*32 + col] = sr;
        sv = sr; bv = Wl[d*128 + c] * lb[c];
        Sv = g_Sl; Bv = g_Bl;
    } else {                   // out (k3, layout unchanged)
        d = bid - 640;
        float sr = tf32r(Wo[d*128 + c] * cw[c]);
        g_Wor[d*128 + c] = sr;
        sv = sr; bv = Wo[d*128 + c] * cb[c];
        Sv = g_So; Bv = g_Bo;
    }
    r1[c] = sv; r2[c] = bv;
    __syncthreads();
    for (int s = 64; s > 0; s >>= 1){
        if (c < s){ r1[c] += r1[c+s]; r2[c] += r2[c+s]; }
        __syncthreads();
    }
    if (c == 0){ Sv[d] = r1[0]; Bv[d] = r2[0]; }
}

// ---------------- k1pg: proj+gate, bulk-copy staging, 512 threads ------------
// smem: A0@0 A1@16384 | B0@32768 B1@65536 (end 98304) | mbar@98304 (16B)
//       smu@98432 sinv@98944 cS1@99456 cB1@99968 cS2@100480 cB2@100992 smk@101504
#define K1PG_SMEM 102016

__global__ void __launch_bounds__(512, 1)
k1pg_kernel(const float* __restrict__ mask){
    extern __shared__ char sm[];
    float* smu  = (float*)(sm + 98432);
    float* sinv = (float*)(sm + 98944);
    float* cS1  = (float*)(sm + 99456);
    float* cB1  = (float*)(sm + 99968);
    float* cS2  = (float*)(sm + 100480);
    float* cB2  = (float*)(sm + 100992);
    uint32_t sbase = smem_u32(sm);
    uint32_t mb    = sbase + 98304;

    int t = threadIdx.x, wid = t >> 5, lane = t & 31;
    int g = lane >> 2, t4 = lane & 3;
    int WM = (wid >> 2) * 32, WN = (wid & 3) * 32;
    int m0 = blockIdx.x * 128;
    int y  = blockIdx.y;
    const float* Wy = &g_Wc[y][0];
    float* smk = (float*)(sm + 101504);

    if (t == 0){ MBARRIER_INIT(mb, 1); MBARRIER_INIT(mb + 8, 1); }
    if (t < 128){
        smu[t]  = g_mu[m0 + t];
        sinv[t] = g_inv[m0 + t];
        smk[t]  = mask[m0 + t];
        int d   = y*128 + t;
        cS1[t] = g_Sp[d]; cB1[t] = g_Bp[d];
        cS2[t] = g_Sg[d]; cB2[t] = g_Bg[d];
    }
    __syncthreads();

    #define K1_ISSUE(kb, buf) do { if (t == 0){                                \
        MBARRIER_EXPECT_TX(mb + (buf)*8, 49152);                               \
        bulk_g2s(sbase + (buf)*16384,                                          \
                 g_x + (size_t)(kb)*GX_KB + (size_t)m0*32, 16384, mb + (buf)*8); \
        bulk_g2s(sbase + 32768 + (buf)*32768,                                  \
                 Wy + (size_t)(kb)*8192, 32768, mb + (buf)*8); } } while(0)

    float accP[2][4][4], accG[2][4][4];
    #pragma unroll
    for (int mi = 0; mi < 2; mi++)
        #pragma unroll
        for (int ni = 0; ni < 4; ni++)
            #pragma unroll
            for (int r = 0; r < 4; r++){ accP[mi][ni][r] = 0.f; accG[mi][ni][r] = 0.f; }

    K1_ISSUE(0, 0);

    #pragma unroll
    for (int kb = 0; kb < 4; kb++){
        if (kb + 1 < 4) K1_ISSUE(kb+1, (kb+1)&1);
        MBARRIER_WAIT_PARITY(mb + (kb&1)*8, (kb>>1)&1);

        const uint32_t* Au = (const uint32_t*)(sm + (kb&1)*16384);
        const uint32_t* Bu = (const uint32_t*)(sm + 32768 + (kb&1)*32768);
        #pragma unroll
        for (int k8 = 0; k8 < 4; k8++){
            int p0 = (k8*8 + t4     + 4*g) & 31;
            int p1 = (k8*8 + t4 + 4 + 4*g) & 31;
            uint32_t af[2][4];
            #pragma unroll
            for (int mi = 0; mi < 2; mi++){
                int R = WM + mi*16 + g;
                af[mi][0] = Au[R*32 + p0];       af[mi][1] = Au[(R+8)*32 + p0];
                af[mi][2] = Au[R*32 + p1];       af[mi][3] = Au[(R+8)*32 + p1];
            }
            #pragma unroll
            for (int ni = 0; ni < 4; ni++){
                int rP = WN + ni*8 + g;
                uint32_t bfP[2] = { Bu[rP*32 + p0],       Bu[rP*32 + p1] };
                uint32_t bfG[2] = { Bu[(rP+128)*32 + p0], Bu[(rP+128)*32 + p1] };
                #pragma unroll
                for (int mi = 0; mi < 2; mi++){
                    mma_tf32(accP[mi][ni], af[mi], bfP);
                    mma_tf32(accG[mi][ni], af[mi], bfG);
                }
            }
        }
        __syncthreads();
    }
    #undef K1_ISSUE

    // epilogue: write to k-blocked rotated g_a/g_b
    float* dst = (y == 0) ? g_a : g_b;
    int iGlob  = m0 >> 9;                    // constant per CTA
    int irot   = 4*(iGlob & 7);
    #pragma unroll
    for (int mi = 0; mi < 2; mi++){
        int m = WM + mi*16 + g;
        int k0 = (m0 & 511) + m, k1 = k0 + 8;
        size_t o0 = (size_t)(k0 >> 5)*16384 + (size_t)iGlob*32 + (((k0 & 31) + irot) & 31);
        size_t o1 = (size_t)(k1 >> 5)*16384 + (size_t)iGlob*32 + (((k1 & 31) + irot) & 31);
        float mu0 = smu[m],   iv0 = sinv[m],   mk0 = smk[m];
        float mu1 = smu[m+8], iv1 = sinv[m+8], mk1 = smk[m+8];
        #pragma unroll
        for (int ni = 0; ni < 4; ni++){
            int dl = WN + ni*8 + 2*t4, dl1 = dl + 1;
            float S0 = cS1[dl], S1 = cS1[dl1], B0 = cB1[dl], B1 = cB1[dl1];
            float G0 = cS2[dl], G1 = cS2[dl1], H0 = cB2[dl], H1 = cB2[dl1];
            float p00 = iv0*(accP[mi][ni][0] - mu0*S0) + B0;
            float p01 = iv0*(accP[mi][ni][1] - mu0*S1) + B1;
            float p10 = iv1*(accP[mi][ni][2] - mu1*S0) + B0;
            float p11 = iv1*(accP[mi][ni][3] - mu1*S1) + B1;
            float q00 = iv0*(accG[mi][ni][0] - mu0*G0) + H0;
            float q01 = iv0*(accG[mi][ni][1] - mu0*G1) + H1;
            float q10 = iv1*(accG[mi][ni][2] - mu1*G0) + H0;
            float q11 = iv1*(accG[mi][ni][3] - mu1*G1) + H1;
            dst[(size_t)dl *PLANE + o0] = tf32r(p00*mk0*sigmoidf_fast(q00));
            dst[(size_t)dl1*PLANE + o0] = tf32r(p01*mk0*sigmoidf_fast(q01));
            dst[(size_t)dl *PLANE + o1] = tf32r(p10*mk1*sigmoidf_fast(q10));
            dst[(size_t)dl1*PLANE + o1] = tf32r(p11*mk1*sigmoidf_fast(q11));
        }
    }
}

// ---------------- merged: k2 (bids 0..1023) + k1gl (bids 1024..3071) ---------
// k2 role:  A0@0 A1@16384 B0@32768 B1@65536 (end 98304) | mbar@98304
// k1gl role: A0@0 A1@16384 B0@32768 B1@49152 (end 65536) | mbar@65536 |
//            sgs@65568 (66560) | smu@132608 sinv@133120 cS1@133632 cB1@134144
#define KM_SMEM 134656

__global__ void __launch_bounds__(512, 1)
k2gl_kernel(){
    extern __shared__ char sm[];
    uint32_t sbase = smem_u32(sm);

    int t = threadIdx.x, wid = t >> 5, lane = t & 31;
    int g = lane >> 2, t4 = lane & 3;
    int bid = blockIdx.x;

    if (bid < 1024){
        // ================= k2 role: triangle GEMM, bulk staging ===============
        uint32_t mb = sbase + 98304;
        int WM = (wid >> 2) * 32, WN = (wid & 3) * 64;
        int c  = bid >> 3;
        int i0 = ((bid >> 1) & 3) * 128;
        int j0 = (bid & 1) * 256;
        const float* Ap = g_a + (size_t)c*PLANE;
        const float* Bp = g_b + (size_t)c*PLANE;

        if (t == 0){ MBARRIER_INIT(mb, 1); MBARRIER_INIT(mb + 8, 1); }
        __syncthreads();

        #define K2_ISSUE(kb, buf) do { if (t == 0){                            \
            MBARRIER_EXPECT_TX(mb + (buf)*8, 49152);                           \
            bulk_g2s(sbase + (buf)*16384,                                      \
                     Ap + (size_t)(kb)*16384 + (size_t)i0*32, 16384, mb + (buf)*8); \
            bulk_g2s(sbase + 32768 + (buf)*32768,                              \
                     Bp + (size_t)(kb)*16384 + (size_t)j0*32, 32768, mb + (buf)*8); } } while(0)

        float acc[2][8][4];
        #pragma unroll
        for (int mi = 0; mi < 2; mi++)
            #pragma unroll
            for (int ni = 0; ni < 8; ni++)
                #pragma unroll
                for (int r = 0; r < 4; r++) acc[mi][ni][r] = 0.f;

        K2_ISSUE(0, 0);

        for (int kb = 0; kb < 16; kb++){
            if (kb + 1 < 16) K2_ISSUE(kb+1, (kb+1)&1);
            MBARRIER_WAIT_PARITY(mb + (kb&1)*8, (kb>>1)&1);

            const uint32_t* Au = (const uint32_t*)(sm + (kb&1)*16384);
            const uint32_t* Bu = (const uint32_t*)(sm + 32768 + (kb&1)*32768);
            #pragma unroll
            for (int k8 = 0; k8 < 4; k8++){
                int p0 = (k8*8 + t4     + 4*g) & 31;
                int p1 = (k8*8 + t4 + 4 + 4*g) & 31;
                uint32_t af[2][4];
                #pragma unroll
                for (int mi = 0; mi < 2; mi++){
                    int R = WM + mi*16 + g;
                    af[mi][0] = Au[R*32 + p0];   af[mi][1] = Au[(R+8)*32 + p0];
                    af[mi][2] = Au[R*32 + p1];   af[mi][3] = Au[(R+8)*32 + p1];
                }
                uint32_t bf[8][2];
                #pragma unroll
                for (int ni = 0; ni < 8; ni++){
                    int rB = WN + ni*8 + g;
                    bf[ni][0] = Bu[rB*32 + p0];  bf[ni][1] = Bu[rB*32 + p1];
                }
                #pragma unroll
                for (int mi = 0; mi < 2; mi++)
                    #pragma unroll
                    for (int ni = 0; ni < 8; ni++)
                        mma_tf32(acc[mi][ni], af[mi], bf[ni]);
            }
            __syncthreads();
        }
        #undef K2_ISSUE

        float* Tp = g_t + (size_t)c*PLANE;
        #pragma unroll
        for (int mi = 0; mi < 2; mi++){
            int r0 = i0 + WM + mi*16 + g;
            #pragma unroll
            for (int ni = 0; ni < 8; ni++){
                int cc = j0 + WN + ni*8 + 2*t4;
                *(float2*)(Tp + (size_t)r0*NN + cc)     = make_float2(acc[mi][ni][0], acc[mi][ni][1]);
                *(float2*)(Tp + (size_t)(r0+8)*NN + cc) = make_float2(acc[mi][ni][2], acc[mi][ni][3]);
            }
        }
    } else {
        // ================= k1gl role: glin gate, bulk staging =================
        uint32_t mb = sbase + 65536;
        float* sgs  = (float*)(sm + 65568);
        float* smu  = (float*)(sm + 132608);
        float* sinv = (float*)(sm + 133120);
        float* cS1  = (float*)(sm + 133632);
        float* cB1  = (float*)(sm + 134144);

        int WM = (wid >> 2) * 32, WN = (wid & 3) * 32;
        int m0 = (bid - 1024) * 128;

        if (t == 0){ MBARRIER_INIT(mb, 1); MBARRIER_INIT(mb + 8, 1); }
        if (t < 128){
            smu[t]  = g_mu[m0 + t];
            sinv[t] = g_inv[m0 + t];
            cS1[t] = g_Sl[t]; cB1[t] = g_Bl[t];
        }
        __syncthreads();

        #define K1G_ISSUE(kb, buf) do { if (t == 0){                           \
            MBARRIER_EXPECT_TX(mb + (buf)*8, 32768);                           \
            bulk_g2s(sbase + (buf)*16384,                                      \
                     g_x + (size_t)(kb)*GX_KB + (size_t)m0*32, 16384, mb + (buf)*8); \
            bulk_g2s(sbase + 32768 + (buf)*16384,                              \
                     g_Wlr + (size_t)(kb)*4096, 16384, mb + (buf)*8); } } while(0)

        float acc[2][4][4];
        #pragma unroll
        for (int mi = 0; mi < 2; mi++)
            #pragma unroll
            for (int ni = 0; ni < 4; ni++)
                #pragma unroll
                for (int r = 0; r < 4; r++) acc[mi][ni][r] = 0.f;

        K1G_ISSUE(0, 0);

        #pragma unroll
        for (int kb = 0; kb < 4; kb++){
            if (kb + 1 < 4) K1G_ISSUE(kb+1, (kb+1)&1);
            MBARRIER_WAIT_PARITY(mb + (kb&1)*8, (kb>>1)&1);

            const uint32_t* Au = (const uint32_t*)(sm + (kb&1)*16384);
            const uint32_t* Bu = (const uint32_t*)(sm + 32768 + (kb&1)*16384);
            #pragma unroll
            for (int k8 = 0; k8 < 4; k8++){
                int p0 = (k8*8 + t4     + 4*g) & 31;
                int p1 = (k8*8 + t4 + 4 + 4*g) & 31;
                uint32_t af[2][4];
                #pragma unroll
                for (int mi = 0; mi < 2; mi++){
                    int R = WM + mi*16 + g;
                    af[mi][0] = Au[R*32 + p0];   af[mi][1] = Au[(R+8)*32 + p0];
                    af[mi][2] = Au[R*32 + p1];   af[mi][3] = Au[(R+8)*32 + p1];
                }
                #pragma unroll
                for (int ni = 0; ni < 4; ni++){
                    int rB = WN + ni*8 + g;
                    uint32_t bf[2] = { Bu[rB*32 + p0], Bu[rB*32 + p1] };
                    #pragma unroll
                    for (int mi = 0; mi < 2; mi++)
                        mma_tf32(acc[mi][ni], af[mi], bf);
                }
            }
            __syncthreads();
        }
        #undef K1G_ISSUE

        #pragma unroll
        for (int mi = 0; mi < 2; mi++){
            int m = WM + mi*16 + g;
            float mu0 = smu[m],   iv0 = sinv[m];
            float mu1 = smu[m+8], iv1 = sinv[m+8];
            #pragma unroll
            for (int ni = 0; ni < 4; ni++){
                int dl = WN + ni*8 + 2*t4, dl1 = dl + 1;
                float S0 = cS1[dl], S1 = cS1[dl1], B0 = cB1[dl], B1 = cB1[dl1];
                sgs[m*130 + dl]      = sigmoidf_fast(iv0*(acc[mi][ni][0] - mu0*S0) + B0);
                sgs[m*130 + dl1]     = sigmoidf_fast(iv0*(acc[mi][ni][1] - mu0*S1) + B1);
                sgs[(m+8)*130 + dl]  = sigmoidf_fast(iv1*(acc[mi][ni][2] - mu1*S0) + B0);
                sgs[(m+8)*130 + dl1] = sigmoidf_fast(iv1*(acc[mi][ni][3] - mu1*S1) + B1);
            }
        }
        __syncthreads();
        float* dst = g_sg + (size_t)m0 * 128;
        #pragma unroll
        for (int u = 0; u < 32; u++){
            int idx = t + u*512;
            int m = idx >> 7, d = idx & 127;
            dst[idx] = sgs[m*130 + d];
        }
    }
}

// ---------------- k3: tf32 mma out-GEMM + LN-fold + gate (unchanged) ---------
#define K3_SMEM 70656

__global__ void __launch_bounds__(256, 2)
k3_kernel(float* __restrict__ out){
    extern __shared__ char sm[];
    float* xs  = (float*)sm;                 // [c 64][pos 128+4]
    float* ws  = (float*)(sm + 33792);       // [d 128][c 64+4]
    float* sS1 = (float*)(sm + 68608);
    float* sS2 = (float*)(sm + 69120);
    float* cS  = (float*)(sm + 69632);
    float* cB  = (float*)(sm + 70144);
    const uint32_t* wsu = (const uint32_t*)ws;
    uint32_t sbase = smem_u32(sm);

    int t = threadIdx.x, wid = t >> 5, lane = t & 31;
    int g = lane >> 2, t4 = lane & 3;
    int WM = (wid >> 2) * 64, WN = (wid & 3) * 32;
    int pos0 = blockIdx.x * 128;

    if (t < 128){ cS[t] = g_So[t]; cB[t] = g_Bo[t]; }

    float acc[4][4][4];
    #pragma unroll
    for (int mi = 0; mi < 4; mi++)
        #pragma unroll
        for (int ni = 0; ni < 4; ni++)
            #pragma unroll
            for (int r = 0; r < 4; r++) acc[mi][ni][r] = 0.f;

    for (int cc = 0; cc < 2; cc++){
        #pragma unroll
        for (int u = 0; u < 8; u++){
            int idx = t + u*256;
            int row = idx >> 5, f4 = idx & 31;
            cp16(sbase + (row*132 + f4*4)*4,
                 g_t + (size_t)(cc*64 + row)*PLANE + pos0 + f4*4);
        }
        #pragma unroll
        for (int u = 0; u < 8; u++){
            int idx = t + u*256;
            int row = idx >> 4, f4 = idx & 15;
            cp16(sbase + 33792 + (row*68 + f4*4)*4,
                 g_Wor + (size_t)row*128 + cc*64 + f4*4);
        }
        cp_commit(); cp_wait<0>();
        __syncthreads();

        if (t < 128){
            float s = 0.f, q = 0.f;
            #pragma unroll 8
            for (int c = 0; c < 64; c++){ float v = xs[c*132 + t]; s += v; q += v*v; }
            if (cc == 0){ sS1[t] = s; sS2[t] = q; }
            else        { sS1[t] += s; sS2[t] += q; }
        }

        #pragma unroll
        for (int k8 = 0; k8 < 8; k8++){
            int kof = k8*8 + t4;
            uint32_t bfr[4][2];
            #pragma unroll
            for (int ni = 0; ni < 4; ni++){
                int bb = (WN + ni*8 + g)*68 + kof;
                bfr[ni][0] = wsu[bb]; bfr[ni][1] = wsu[bb + 4];
            }
            #pragma unroll
            for (int mi = 0; mi < 4; mi++){
                int m = WM + mi*16 + g;
                float x0 = xs[kof*132 + m],       x1 = xs[kof*132 + m + 8];
                float x2 = xs[(kof+4)*132 + m],   x3 = xs[(kof+4)*132 + m + 8];
                uint32_t ah[4] = { f2tf32(x0), f2tf32(x1), f2tf32(x2), f2tf32(x3) };
                #pragma unroll
                for (int ni = 0; ni < 4; ni++)
                    mma_tf32(acc[mi][ni], ah, bfr[ni]);
            }
        }
        __syncthreads();
    }

    const float* sgp = g_sg + (size_t)pos0 * 128;
    float* outp = out + (size_t)pos0 * 128;
    #pragma unroll
    for (int mi = 0; mi < 4; mi++){
        int m = WM + mi*16 + g;
        float mu0 = sS1[m]   * (1.f/128.f);
        float mu1 = sS1[m+8] * (1.f/128.f);
        float iv0 = rsqrtf(sS2[m]  *(1.f/128.f) - mu0*mu0 + 1e-5f);
        float iv1 = rsqrtf(sS2[m+8]*(1.f/128.f) - mu1*mu1 + 1e-5f);
        #pragma unroll
        for (int ni = 0; ni < 4; ni++){
            int dl = WN + ni*8 + 2*t4, dl1 = dl + 1;
            float S0 = cS[dl], S1 = cS[dl1], B0 = cB[dl], B1 = cB[dl1];
            float2 sg0 = *(const float2*)(sgp + (size_t)m*128 + dl);
            float2 sg1 = *(const float2*)(sgp + (size_t)(m+8)*128 + dl);
            float o00 = (iv0*(acc[mi][ni][0] - mu0*S0) + B0) * sg0.x;
            float o01 = (iv0*(acc[mi][ni][1] - mu0*S1) + B1) * sg0.y;
            float o10 = (iv1*(acc[mi][ni][2] - mu1*S0) + B0) * sg1.x;
            float o11 = (iv1*(acc[mi][ni][3] - mu1*S1) + B1) * sg1.y;
            *(float2*)(outp + (size_t)m*128 + dl)     = make_float2(o00, o01);
            *(float2*)(outp + (size_t)(m+8)*128 + dl) = make_float2(o10, o11);
        }
    }
}

// ---------------- launch -----------------------------------------------------
extern "C" void kernel_launch(void* const* d_in, const int* in_sizes, int n_in,
                              void* d_out, int out_size){
    const float* act  = (const float*)d_in[0];
    const float* mask = (const float*)d_in[1];
    const float* lnw  = (const float*)d_in[2];
    const float* lnb  = (const float*)d_in[3];
    const float* Wp   = (const float*)d_in[4];
    const float* Wg   = (const float*)d_in[5];
    const float* lcw  = (const float*)d_in[6];
    const float* lcb  = (const float*)d_in[7];
    const float* Wo   = (const float*)d_in[8];
    const float* Wl   = (const float*)d_in[9];

    cudaFuncSetAttribute(k1pg_kernel, cudaFuncAttributeMaxDynamicSharedMemorySize, K1PG_SMEM);
    cudaFuncSetAttribute(k2gl_kernel, cudaFuncAttributeMaxDynamicSharedMemorySize, KM_SMEM);
    cudaFuncSetAttribute(k3_kernel,   cudaFuncAttributeMaxDynamicSharedMemorySize, K3_SMEM);

    prep_kernel<<<768, 128>>>(lnw, lnb, Wp, Wg, lcw, lcb, Wo, Wl);
    k0_kernel<<<32768, 256>>>(act);
    k1pg_kernel<<<dim3(2048, 2), 512, K1PG_SMEM>>>(mask);
    k2gl_kernel<<<3072, 512, KM_SMEM>>>();
    k3_kernel<<<2048, 256, K3_SMEM>>>((float*)d_out);
}